// round 1
// baseline (speedup 1.0000x reference)
#include <cuda_runtime.h>

// DynamiConv: out[b,o,y,x] = gate(b,y,x) * conv3x3(x,W)[b,o,y,x] + bias[o]
// gate = conv3x3(sigmoid(x), dweight)   (scalar gate per spatial position)
//
// Shapes: x[8,32,256,256] f32, weight[32,32,3,3], dweight[1,32,3,3], bias[32]
// out[8,32,256,256] f32.

#define B_   8
#define C_   32
#define O_   32
#define HW_  256
#define TILE 16
#define INT_ 18          // TILE + 2 (halo)
#define XS_PER_C (INT_*INT_)   // 324
#define WROW 12          // padded per-(c,o) weight row (9 used), float4-aligned

// smem layout (floats):
//   xs  [32 * 324]            = 10368
//   ws  [(c*32+o)*12 + j]     = 12288
//   dws [c*12 + j]            = 384
//   bs  [32]                  = 32
#define SM_XS   0
#define SM_WS   (SM_XS + C_*XS_PER_C)
#define SM_DWS  (SM_WS + C_*O_*WROW)
#define SM_BS   (SM_DWS + C_*WROW)
#define SM_FLOATS (SM_BS + 32)

__device__ __forceinline__ float sigf(float v) {
    return __fdividef(1.0f, 1.0f + __expf(-v));
}

__global__ __launch_bounds__(256, 2)
void dynamiconv_kernel(const float* __restrict__ x,
                       const float* __restrict__ weight,
                       const float* __restrict__ dweight,
                       const float* __restrict__ bias,
                       float* __restrict__ out)
{
    extern __shared__ float sm[];
    float* xs  = sm + SM_XS;
    float* ws  = sm + SM_WS;
    float* dws = sm + SM_DWS;
    float* bs  = sm + SM_BS;

    const int tid = threadIdx.x;
    const int b   = blockIdx.z;
    const int ty0 = blockIdx.y * TILE;
    const int tx0 = blockIdx.x * TILE;

    // ---- load weights into smem, re-laid-out [c][o][12] for float4 access ----
    #pragma unroll 4
    for (int i = tid; i < O_*C_*9; i += 256) {
        int o = i / (C_*9);
        int r = i - o*(C_*9);
        int c = r / 9;
        int j = r - c*9;
        ws[(c*O_ + o)*WROW + j] = weight[i];
    }
    for (int i = tid; i < C_*9; i += 256) {
        int c = i / 9, j = i - c*9;
        dws[c*WROW + j] = dweight[i];
    }
    if (tid < 32) bs[tid] = bias[tid];

    // ---- load halo'd x tile: xs[c][iy][ix], zero padded at image border ----
    const float* xb = x + (size_t)b * (C_*HW_*HW_);
    #pragma unroll 4
    for (int i = tid; i < C_*XS_PER_C; i += 256) {
        int c  = i / XS_PER_C;
        int r  = i - c*XS_PER_C;
        int iy = r / INT_;
        int ix = r - iy*INT_;
        int gy = ty0 + iy - 1;
        int gx = tx0 + ix - 1;
        float v = 0.0f;
        if ((unsigned)gy < (unsigned)HW_ && (unsigned)gx < (unsigned)HW_)
            v = xb[(size_t)c*(HW_*HW_) + gy*HW_ + gx];
        xs[i] = v;
    }
    __syncthreads();

    const int py = tid >> 4;   // 0..15
    const int px = tid & 15;   // 0..15

    float acc[O_];
    #pragma unroll
    for (int o = 0; o < O_; o++) acc[o] = 0.0f;
    float gate = 0.0f;

    for (int c = 0; c < C_; c++) {
        const float* xc = xs + c*XS_PER_C + py*INT_ + px;
        float v0 = xc[0],      v1 = xc[1],        v2 = xc[2];
        float v3 = xc[INT_],   v4 = xc[INT_+1],   v5 = xc[INT_+2];
        float v6 = xc[2*INT_], v7 = xc[2*INT_+1], v8 = xc[2*INT_+2];

        const float* dwc = dws + c*WROW;
        gate = fmaf(dwc[0], sigf(v0), gate);
        gate = fmaf(dwc[1], sigf(v1), gate);
        gate = fmaf(dwc[2], sigf(v2), gate);
        gate = fmaf(dwc[3], sigf(v3), gate);
        gate = fmaf(dwc[4], sigf(v4), gate);
        gate = fmaf(dwc[5], sigf(v5), gate);
        gate = fmaf(dwc[6], sigf(v6), gate);
        gate = fmaf(dwc[7], sigf(v7), gate);
        gate = fmaf(dwc[8], sigf(v8), gate);

        const float4* wp = (const float4*)(ws + (size_t)c*O_*WROW);
        #pragma unroll
        for (int o = 0; o < O_; o++) {
            float4 wa = wp[o*3 + 0];                 // w[0..3]
            float4 wb = wp[o*3 + 1];                 // w[4..7]
            float  w8 = ((const float*)wp)[o*WROW + 8];
            float a = acc[o];
            a = fmaf(wa.x, v0, a);
            a = fmaf(wa.y, v1, a);
            a = fmaf(wa.z, v2, a);
            a = fmaf(wa.w, v3, a);
            a = fmaf(wb.x, v4, a);
            a = fmaf(wb.y, v5, a);
            a = fmaf(wb.z, v6, a);
            a = fmaf(wb.w, v7, a);
            a = fmaf(w8,   v8, a);
            acc[o] = a;
        }
    }

    float* ob = out + (size_t)b*(O_*HW_*HW_) + (ty0 + py)*HW_ + (tx0 + px);
    #pragma unroll
    for (int o = 0; o < O_; o++)
        ob[(size_t)o*(HW_*HW_)] = fmaf(gate, acc[o], bs[o]);
}

extern "C" void kernel_launch(void* const* d_in, const int* in_sizes, int n_in,
                              void* d_out, int out_size)
{
    const float* x       = (const float*)d_in[0];
    const float* weight  = (const float*)d_in[1];
    const float* dweight = (const float*)d_in[2];
    const float* bias    = (const float*)d_in[3];
    float* out = (float*)d_out;

    const int smem_bytes = SM_FLOATS * (int)sizeof(float);   // ~92.4 KB
    cudaFuncSetAttribute(dynamiconv_kernel,
                         cudaFuncAttributeMaxDynamicSharedMemorySize, smem_bytes);

    dim3 grid(HW_/TILE, HW_/TILE, B_);   // 16 x 16 x 8 = 2048 CTAs
    dim3 block(256);
    dynamiconv_kernel<<<grid, block, smem_bytes>>>(x, weight, dweight, bias, out);
}

// round 2
// speedup vs baseline: 1.0300x; 1.0300x over previous
#include <cuda_runtime.h>

// DynamiConv: out[b,o,y,x] = gate(b,y,x) * conv3x3(x,W)[b,o,y,x] + bias[o]
// gate = conv3x3(sigmoid(x), dweight)
//
// x[8,32,256,256] f32, weight[32,32,3,3], dweight[1,32,3,3], bias[32] -> out[8,32,256,256]
//
// Round 2: 4px x 8o register blocking, o-pair packed fma.rn.f32x2 (sm_100+ FFMA2),
// tanh-based sigmoid (1 MUFU), conflict-free vector LDS.

#define B_   8
#define C_   32
#define O_   32
#define HW_  256
#define TILE 16
#define XSTR 20                 // padded row stride of halo tile (18 used)
#define XS_PER_C (18*XSTR)      // 360
#define GSTR 17                 // gate smem stride (conflict-free)

// smem layout (floats)
#define SM_XS   0
#define SM_WP   (SM_XS + C_*XS_PER_C)          // 11520
#define SM_DWS  (SM_WP + C_*16*20)             // +10240 = 21760
#define SM_BS   (SM_DWS + C_*9)                // +288   = 22048
#define SM_GS   (SM_BS + 32)                   // +32    = 22080
#define SM_FLOATS (SM_GS + 16*GSTR)            // +272   = 22352  (~89.4 KB)

typedef unsigned long long ull;

__device__ __forceinline__ ull pk(float lo, float hi) {
    ull r;
    asm("mov.b64 %0, {%1, %2};" : "=l"(r)
        : "r"(__float_as_uint(lo)), "r"(__float_as_uint(hi)));
    return r;
}
__device__ __forceinline__ ull f2(ull a, ull b, ull c) {
    ull d;
    asm("fma.rn.f32x2 %0, %1, %2, %3;" : "=l"(d) : "l"(a), "l"(b), "l"(c));
    return d;
}
__device__ __forceinline__ void upk(ull v, float& lo, float& hi) {
    unsigned l, h;
    asm("mov.b64 {%0, %1}, %2;" : "=r"(l), "=r"(h) : "l"(v));
    lo = __uint_as_float(l); hi = __uint_as_float(h);
}
__device__ __forceinline__ float sigf(float v) {
    float t;
    asm("tanh.approx.f32 %0, %1;" : "=f"(t) : "f"(v * 0.5f));
    return fmaf(0.5f, t, 0.5f);
}

__global__ __launch_bounds__(256, 2)
void dynamiconv_kernel(const float* __restrict__ x,
                       const float* __restrict__ weight,
                       const float* __restrict__ dweight,
                       const float* __restrict__ bias,
                       float* __restrict__ out)
{
    extern __shared__ float sm[];
    float* xs  = sm + SM_XS;
    float* wp  = sm + SM_WP;    // [c][opair 0..15][tap*2 + half], row stride 20
    float* dws = sm + SM_DWS;   // [c*9 + j]
    float* bs  = sm + SM_BS;
    float* gs  = sm + SM_GS;    // gate per pixel, stride 17

    const int tid = threadIdx.x;
    const int b   = blockIdx.z;
    const int ty0 = blockIdx.y * TILE;
    const int tx0 = blockIdx.x * TILE;

    // ---- weights -> smem, interleaved as (o even, o odd) pairs per tap ----
    #pragma unroll 4
    for (int i = tid; i < O_*C_*9; i += 256) {
        int o = i / (C_*9);
        int r = i - o*(C_*9);
        int c = r / 9;
        int j = r - c*9;
        wp[(c*16 + (o >> 1))*20 + j*2 + (o & 1)] = weight[i];
    }
    for (int i = tid; i < C_*9; i += 256) dws[i] = dweight[i];
    if (tid < 32) bs[tid] = bias[tid];

    // ---- halo'd x tile: xs[c][iy][ix], row stride 20, zero-padded ----
    const float* xb = x + (size_t)b * (C_*HW_*HW_);
    #pragma unroll 4
    for (int i = tid; i < C_*XS_PER_C; i += 256) {
        int c  = i / XS_PER_C;
        int r  = i - c*XS_PER_C;
        int iy = r / XSTR;
        int ix = r - iy*XSTR;
        float v = 0.0f;
        if (ix < 18) {
            int gy = ty0 + iy - 1;
            int gx = tx0 + ix - 1;
            if ((unsigned)gy < (unsigned)HW_ && (unsigned)gx < (unsigned)HW_)
                v = xb[(size_t)c*(HW_*HW_) + gy*HW_ + gx];
        }
        xs[i] = v;
    }
    __syncthreads();

    // ================= gate pass: 1 thread = 1 pixel =================
    {
        const int py = tid >> 4;
        const int px = tid & 15;
        float gate = 0.0f;
        for (int c = 0; c < C_; c++) {
            const float* xc  = xs + c*XS_PER_C + py*XSTR + px;
            const float* dwc = dws + c*9;
            gate = fmaf(dwc[0], sigf(xc[0]),        gate);
            gate = fmaf(dwc[1], sigf(xc[1]),        gate);
            gate = fmaf(dwc[2], sigf(xc[2]),        gate);
            gate = fmaf(dwc[3], sigf(xc[XSTR]),     gate);
            gate = fmaf(dwc[4], sigf(xc[XSTR+1]),   gate);
            gate = fmaf(dwc[5], sigf(xc[XSTR+2]),   gate);
            gate = fmaf(dwc[6], sigf(xc[2*XSTR]),   gate);
            gate = fmaf(dwc[7], sigf(xc[2*XSTR+1]), gate);
            gate = fmaf(dwc[8], sigf(xc[2*XSTR+2]), gate);
        }
        gs[py*GSTR + px] = gate;
    }

    // ================= conv pass: 1 thread = 4 px x 8 o =================
    const int sy  = tid & 15;          // pixel row in tile
    const int sx0 = ((tid >> 4) & 3) * 4;  // pixel col start (strip of 4)
    const int og  = tid >> 6;          // o-group: channels og*8 .. og*8+7

    ull acc2[4][4];                    // [o-pair q][pixel p]
    #pragma unroll
    for (int q = 0; q < 4; q++)
        #pragma unroll
        for (int p = 0; p < 4; p++) acc2[q][p] = 0ULL;

    #pragma unroll 1
    for (int c = 0; c < C_; c++) {
        const float* xc = xs + c*XS_PER_C + sy*XSTR + sx0;
        float4 a0 = *(const float4*)(xc);
        float2 e0 = *(const float2*)(xc + 4);
        float4 a1 = *(const float4*)(xc + XSTR);
        float2 e1 = *(const float2*)(xc + XSTR + 4);
        float4 a2 = *(const float4*)(xc + 2*XSTR);
        float2 e2 = *(const float2*)(xc + 2*XSTR + 4);

        ull vd[3][6];
        vd[0][0]=pk(a0.x,a0.x); vd[0][1]=pk(a0.y,a0.y); vd[0][2]=pk(a0.z,a0.z);
        vd[0][3]=pk(a0.w,a0.w); vd[0][4]=pk(e0.x,e0.x); vd[0][5]=pk(e0.y,e0.y);
        vd[1][0]=pk(a1.x,a1.x); vd[1][1]=pk(a1.y,a1.y); vd[1][2]=pk(a1.z,a1.z);
        vd[1][3]=pk(a1.w,a1.w); vd[1][4]=pk(e1.x,e1.x); vd[1][5]=pk(e1.y,e1.y);
        vd[2][0]=pk(a2.x,a2.x); vd[2][1]=pk(a2.y,a2.y); vd[2][2]=pk(a2.z,a2.z);
        vd[2][3]=pk(a2.w,a2.w); vd[2][4]=pk(e2.x,e2.x); vd[2][5]=pk(e2.y,e2.y);

        const ull* wq = (const ull*)(wp + (c*16 + og*4)*20);
        #pragma unroll
        for (int q = 0; q < 4; q++) {
            ulonglong2 w01 = ((const ulonglong2*)wq)[0];   // taps 0,1
            ulonglong2 w23 = ((const ulonglong2*)wq)[1];   // taps 2,3
            ulonglong2 w45 = ((const ulonglong2*)wq)[2];   // taps 4,5
            ulonglong2 w67 = ((const ulonglong2*)wq)[3];   // taps 6,7
            ull        w8  = wq[8];                        // tap 8
            #pragma unroll
            for (int p = 0; p < 4; p++) {
                ull t = acc2[q][p];
                t = f2(vd[0][p+0], w01.x, t);
                t = f2(vd[0][p+1], w01.y, t);
                t = f2(vd[0][p+2], w23.x, t);
                t = f2(vd[1][p+0], w23.y, t);
                t = f2(vd[1][p+1], w45.x, t);
                t = f2(vd[1][p+2], w45.y, t);
                t = f2(vd[2][p+0], w67.x, t);
                t = f2(vd[2][p+1], w67.y, t);
                t = f2(vd[2][p+2], w8,    t);
                acc2[q][p] = t;
            }
            wq += 10;
        }
    }

    __syncthreads();   // gs fully written before cross-thread reads

    // ================= epilogue =================
    float g[4];
    #pragma unroll
    for (int p = 0; p < 4; p++) g[p] = gs[sy*GSTR + sx0 + p];

    float* ob = out + (size_t)b*(O_*HW_*HW_) + (size_t)(ty0 + sy)*HW_ + tx0 + sx0;
    #pragma unroll
    for (int q = 0; q < 4; q++) {
        int o = og*8 + 2*q;
        float lo0,hi0, lo1,hi1, lo2,hi2, lo3,hi3;
        upk(acc2[q][0], lo0, hi0);
        upk(acc2[q][1], lo1, hi1);
        upk(acc2[q][2], lo2, hi2);
        upk(acc2[q][3], lo3, hi3);
        float b0 = bs[o], b1 = bs[o+1];
        float4 r0 = { fmaf(g[0],lo0,b0), fmaf(g[1],lo1,b0), fmaf(g[2],lo2,b0), fmaf(g[3],lo3,b0) };
        float4 r1 = { fmaf(g[0],hi0,b1), fmaf(g[1],hi1,b1), fmaf(g[2],hi2,b1), fmaf(g[3],hi3,b1) };
        *(float4*)(ob + (size_t)o    *(HW_*HW_)) = r0;
        *(float4*)(ob + (size_t)(o+1)*(HW_*HW_)) = r1;
    }
}

extern "C" void kernel_launch(void* const* d_in, const int* in_sizes, int n_in,
                              void* d_out, int out_size)
{
    const float* x       = (const float*)d_in[0];
    const float* weight  = (const float*)d_in[1];
    const float* dweight = (const float*)d_in[2];
    const float* bias    = (const float*)d_in[3];
    float* out = (float*)d_out;

    const int smem_bytes = SM_FLOATS * (int)sizeof(float);
    cudaFuncSetAttribute(dynamiconv_kernel,
                         cudaFuncAttributeMaxDynamicSharedMemorySize, smem_bytes);

    dim3 grid(HW_/TILE, HW_/TILE, B_);
    dim3 block(256);
    dynamiconv_kernel<<<grid, block, smem_bytes>>>(x, weight, dweight, bias, out);
}